// round 14
// baseline (speedup 1.0000x reference)
#include <cuda_runtime.h>
#include <cuda_bf16.h>
#include <cstdint>

// Fixed problem shape
#define BB 8
#define NN 4096
#define EE 64
#define KK 32

#define DELTA_V 0.5f
#define DELTA_D 1.5f
#define GAMMA   0.001f

#define G1 256            // blocks for K1/K3
#define TPB 512
#define PTS 128           // points per block

#define K1_X_BYTES   (PTS * EE * 4)            // 32768
#define K1_M_BYTES   (PTS * KK * 4)            // 16384
#define K1_DYN       (K1_X_BYTES + K1_M_BYTES) // 49152
#define K3_C_BYTES   (KK * EE * 4)             // 8192
#define K3_DYN       (K1_X_BYTES + K3_C_BYTES) // 40960

// Scratch ------------------------------------------------------------------
__device__ __align__(256) float g_part[G1 * KK * EE]; // per-block partial sums
__device__ __align__(256) float g_pcnt[G1 * KK];      // per-block counts
__device__ __align__(256) float g_cent[BB * KK * EE]; // normalized centroids
__device__ __align__(256) int   g_lab[BB * NN];       // labels
__device__ float    g_acc[3];               // L_v, L_d, L_r (unnormalized)
__device__ unsigned g_bar = 0;              // finalize counter

// TMA bulk helpers ---------------------------------------------------------
__device__ __forceinline__ uint32_t smem_u32(const void* p) {
    return (uint32_t)__cvta_generic_to_shared(p);
}
__device__ __forceinline__ void mbar_init(uint32_t bar, uint32_t cnt) {
    asm volatile("mbarrier.init.shared.b64 [%0], %1;" :: "r"(bar), "r"(cnt) : "memory");
}
__device__ __forceinline__ void mbar_expect_tx(uint32_t bar, uint32_t bytes) {
    asm volatile("mbarrier.arrive.expect_tx.shared.b64 _, [%0], %1;"
                 :: "r"(bar), "r"(bytes) : "memory");
}
__device__ __forceinline__ void tma_bulk_g2s(uint32_t dst, const void* src,
                                             uint32_t bytes, uint32_t bar) {
    asm volatile("cp.async.bulk.shared::cluster.global.mbarrier::complete_tx::bytes "
                 "[%0], [%1], %2, [%3];"
                 :: "r"(dst), "l"(src), "r"(bytes), "r"(bar) : "memory");
}
__device__ __forceinline__ void fence_async_shared() {
    asm volatile("fence.proxy.async.shared::cta;" ::: "memory");
}
__device__ __forceinline__ void mbar_wait(uint32_t bar, uint32_t parity) {
    asm volatile(
        "{\n\t"
        ".reg .pred P;\n\t"
        "W%=:\n\t"
        "mbarrier.try_wait.parity.shared::cta.b64 P, [%0], %1;\n\t"
        "@P bra D%=;\n\t"
        "bra W%=;\n\t"
        "D%=:\n\t"
        "}"
        :: "r"(bar), "r"(parity) : "memory");
}

// ===========================================================================
// K1: TMA-bulk x + masks -> SMEM; labels from SMEM; sort; bin partial sums.
// ===========================================================================
__global__ void __launch_bounds__(TPB) k_partial(const float* __restrict__ x,
                                                 const float* __restrict__ m) {
    extern __shared__ float smem[];
    float* sx = smem;                     // [PTS*EE]
    float* sm = smem + PTS * EE;          // [PTS*KK]
    __shared__ uint64_t mbar;
    __shared__ int slab[PTS];
    __shared__ int ssorted[PTS];
    __shared__ int sbin[KK], soff[KK], scur[KK];

    int tid = threadIdx.x, lane = tid & 31, warp = tid >> 5;
    int blk = blockIdx.x;
    int pbase = blk * PTS;
    int b = blk >> 5;                     // 32 blocks per batch

    uint32_t bar = smem_u32(&mbar);
    if (tid == 0) { mbar_init(bar, 1); fence_async_shared(); }
    if (tid < KK) sbin[tid] = 0;
    if (blk == 0 && tid < 3) g_acc[tid] = 0.0f;
    __syncthreads();                      // barrier init visible to all

    if (tid == 0) {
        mbar_expect_tx(bar, K1_DYN);
        tma_bulk_g2s(smem_u32(sx), x + (size_t)pbase * EE, K1_X_BYTES, bar);
        tma_bulk_g2s(smem_u32(sm), m + (size_t)pbase * KK, K1_M_BYTES, bar);
    }
    mbar_wait(bar, 0);                    // all threads wait for both copies
    __syncthreads();

    // ---- labels from SMEM: 4 threads per point, dot with k-index ----------
    {
        int p = tid >> 2, j = tid & 3;    // 512 threads = 128 pts x 4
        const float* row = sm + p * KK + j * 8;
        float4 a = *(const float4*)row;
        float4 c = *(const float4*)(row + 4);
        float k0 = (float)(j * 8);
        float s = a.x * k0 + a.y * (k0 + 1.f) + a.z * (k0 + 2.f) + a.w * (k0 + 3.f)
                + c.x * (k0 + 4.f) + c.y * (k0 + 5.f) + c.z * (k0 + 6.f) + c.w * (k0 + 7.f);
        s += __shfl_xor_sync(0xffffffffu, s, 1);
        s += __shfl_xor_sync(0xffffffffu, s, 2);
        if (j == 0) slab[p] = (int)(s + 0.5f);
    }
    __syncthreads();

    // ---- counting sort -----------------------------------------------------
    if (tid < PTS) atomicAdd(&sbin[slab[tid]], 1);
    __syncthreads();
    if (tid < KK) {
        int c = sbin[tid];
        int pref = c;
        #pragma unroll
        for (int o = 1; o < 32; o <<= 1) {
            int nv = __shfl_up_sync(0xffffffffu, pref, o);
            if (lane >= o) pref += nv;
        }
        soff[tid] = pref - c;
        scur[tid] = pref - c;
    }
    __syncthreads();
    if (tid < PTS) {
        int pos = atomicAdd(&scur[slab[tid]], 1);
        ssorted[pos] = tid;
        g_lab[pbase + tid] = slab[tid];   // persist labels for K3
    }
    __syncthreads();

    // ---- per-bin accumulation from SMEM -> private partial slices ----------
    #pragma unroll
    for (int kb = 0; kb < 2; ++kb) {
        int k = warp * 2 + kb;
        int start = soff[k], cnt = sbin[k], end = start + cnt;
        float ax = 0.0f, ay = 0.0f;
        for (int base = start; base < end; base += 4) {
            float2 v0 = {0,0}, v1 = {0,0}, v2 = {0,0}, v3 = {0,0};
            v0 = *(const float2*)(sx + ssorted[base] * EE + lane * 2);
            if (base + 1 < end) v1 = *(const float2*)(sx + ssorted[base+1] * EE + lane * 2);
            if (base + 2 < end) v2 = *(const float2*)(sx + ssorted[base+2] * EE + lane * 2);
            if (base + 3 < end) v3 = *(const float2*)(sx + ssorted[base+3] * EE + lane * 2);
            ax += (v0.x + v1.x) + (v2.x + v3.x);
            ay += (v0.y + v1.y) + (v2.y + v3.y);
        }
        float2 acc = {ax, ay};
        *(float2*)(&g_part[(size_t)blk * (KK*EE) + k * EE + lane * 2]) = acc;
        if (lane == 0) g_pcnt[blk * KK + k] = (float)cnt;
    }
}

// ===========================================================================
// K2: block i reduces (b,k)-row i -> normalized g_cent. 256 blocks x 256 thr.
// ===========================================================================
__global__ void __launch_bounds__(256) k_reduce() {
    __shared__ float part[256];
    __shared__ float s_cntinv;
    int tid = threadIdx.x, lane = tid & 31;
    int rb = blockIdx.x >> 5, rk = blockIdx.x & 31;

    if (tid < 32) {                     // sum 32 partial counts
        float c = __ldcg(&g_pcnt[((rb << 5) | lane) * KK + rk]);
        #pragma unroll
        for (int o = 16; o; o >>= 1) c += __shfl_xor_sync(0xffffffffu, c, o);
        if (lane == 0) s_cntinv = 1.0f / c;
    }

    int e = tid & 63, q = tid >> 6;     // 4 groups of 64, 8 slices each
    float s = 0.0f;
    #pragma unroll
    for (int j = 0; j < 8; ++j)
        s += __ldcg(&g_part[(size_t)((rb << 5) | (q * 8 + j)) * (KK*EE) + rk * EE + e]);
    part[q * 64 + e] = s;
    __syncthreads();
    if (tid < EE) {
        float t = ((part[tid] + part[64 + tid]) + (part[128 + tid] + part[192 + tid]));
        g_cent[rb * (KK*EE) + rk * EE + tid] = t * s_cntinv;
    }
}

// ===========================================================================
// K3: TMA-bulk x + centroids -> SMEM; variance hinge; pairs/reg; finalize.
// ===========================================================================
__global__ void __launch_bounds__(TPB) k_loss(const float* __restrict__ x,
                                              float* __restrict__ out) {
    extern __shared__ float smem[];
    float* sx = smem;                     // [PTS*EE]
    float* sc = smem + PTS * EE;          // [KK*EE] normalized centroids
    __shared__ uint64_t mbar;
    __shared__ float ct[KK * EE];
    __shared__ int   slab[PTS];
    __shared__ float bsum;

    int tid = threadIdx.x, lane = tid & 31;
    int blk = blockIdx.x;
    int pbase = blk * PTS;
    int b = blk >> 5;

    uint32_t bar = smem_u32(&mbar);
    if (tid == 0) { mbar_init(bar, 1); fence_async_shared(); }
    __syncthreads();
    if (tid == 0) {
        mbar_expect_tx(bar, K3_DYN);
        tma_bulk_g2s(smem_u32(sx), x + (size_t)pbase * EE, K1_X_BYTES, bar);
        tma_bulk_g2s(smem_u32(sc), g_cent + (size_t)b * (KK*EE), K3_C_BYTES, bar);
    }
    if (tid < PTS) slab[tid] = g_lab[pbase + tid];   // overlaps the bulk copy
    if (tid == 0) bsum = 0.0f;
    mbar_wait(bar, 0);
    __syncthreads();

    // ---- variance hinge: 16-lane group per point, 2-pt ILP, from SMEM -----
    {
        int gid = tid >> 4, gl = tid & 15;
        float lv = 0.0f;
        #pragma unroll
        for (int it = 0; it < 2; ++it) {
            int iA = it * 64 + gid;
            int iB = iA + 32;
            int labA = slab[iA], labB = slab[iB];
            float4 xA = ((const float4*)sx)[iA * 16 + gl];
            float4 xB = ((const float4*)sx)[iB * 16 + gl];
            float4 cA = ((const float4*)sc)[labA * 16 + gl];
            float4 cB = ((const float4*)sc)[labB * 16 + gl];
            float a0 = xA.x - cA.x, a1 = xA.y - cA.y, a2 = xA.z - cA.z, a3 = xA.w - cA.w;
            float b0 = xB.x - cB.x, b1 = xB.y - cB.y, b2 = xB.z - cB.z, b3 = xB.w - cB.w;
            float sqA = a0 * a0 + a1 * a1 + a2 * a2 + a3 * a3;
            float sqB = b0 * b0 + b1 * b1 + b2 * b2 + b3 * b3;
            #pragma unroll
            for (int o = 8; o; o >>= 1) {
                sqA += __shfl_xor_sync(0xffffffffu, sqA, o);
                sqB += __shfl_xor_sync(0xffffffffu, sqB, o);
            }
            if (gl == 0) {
                float hA = sqrtf(sqA) - DELTA_V;
                float hB = sqrtf(sqB) - DELTA_V;
                if (hA > 0.0f) lv += hA * hA;
                if (hB > 0.0f) lv += hB * hB;
            }
        }
        if (gl == 0) atomicAdd(&bsum, lv);
        __syncthreads();
        if (tid == 0) atomicAdd(&g_acc[0], bsum);
    }

    // ---- pairwise hinge + reg term (one block per batch) ------------------
    if ((blk & 31) == 0) {
        for (int i = tid; i < KK * EE; i += TPB) {
            int e = i >> 5, k = i & 31;
            ct[i] = sc[k * EE + e];            // transposed, lane-contiguous
        }
        __syncthreads();

        float ld = 0.0f, lr = 0.0f;
        #pragma unroll
        for (int rep = 0; rep < 2; ++rep) {
            int pr = rep * TPB + tid;
            int k1 = pr >> 5, k2 = pr & 31;
            float sq = 0.0f;
            if (k1 == k2) {
                #pragma unroll
                for (int e = 0; e < EE; e++) { float v = sc[k1 * EE + e]; sq += v * v; }
                lr += sqrtf(sq);
            } else {
                #pragma unroll
                for (int e = 0; e < EE; e++) {
                    float d = sc[k1 * EE + e] - ct[e * KK + k2];
                    sq += d * d;
                }
                float h = 2.0f * DELTA_D - sqrtf(sq);
                if (h > 0.0f) ld += h * h;
            }
        }
        #pragma unroll
        for (int o = 16; o; o >>= 1) {
            ld += __shfl_xor_sync(0xffffffffu, ld, o);
            lr += __shfl_xor_sync(0xffffffffu, lr, o);
        }
        if (lane == 0) {
            atomicAdd(&g_acc[1], ld);
            atomicAdd(&g_acc[2], lr);
        }
    }

    // ---- finalize: last arrival writes output -----------------------------
    __syncthreads();
    if (tid == 0) {
        __threadfence();
        unsigned r = atomicAdd(&g_bar, 1u);
        if (r == G1 - 1) {
            float Lv = *(volatile float*)&g_acc[0] / (float)(BB * NN);
            float Ld = *(volatile float*)&g_acc[1] / (float)(BB * KK * (KK - 1));
            float Lr = *(volatile float*)&g_acc[2] / (float)(BB * KK);
            out[0] = Lv + Ld + GAMMA * Lr;
            __threadfence();
            atomicExch(&g_bar, 0u);            // ready for next replay
        }
    }
}

// --------------------------------------------------------------------------
extern "C" void kernel_launch(void* const* d_in, const int* in_sizes, int n_in,
                              void* d_out, int out_size) {
    const float* x = (const float*)d_in[0];
    const float* m = (const float*)d_in[1];
    if (in_sizes[0] == BB * NN * KK && in_sizes[1] == BB * NN * EE) {
        x = (const float*)d_in[1];
        m = (const float*)d_in[0];
    }
    cudaFuncSetAttribute(k_partial, cudaFuncAttributeMaxDynamicSharedMemorySize, K1_DYN);
    cudaFuncSetAttribute(k_loss,    cudaFuncAttributeMaxDynamicSharedMemorySize, K3_DYN);
    k_partial<<<G1, TPB, K1_DYN>>>(x, m);
    k_reduce<<<G1, 256>>>();
    k_loss<<<G1, TPB, K3_DYN>>>(x, (float*)d_out);
}